// round 6
// baseline (speedup 1.0000x reference)
#include <cuda_runtime.h>
#include <cuda_bf16.h>
#include <math.h>
#include <stdint.h>

// Problem constants
#define T_SEQ 2048
#define BATCH 2
#define HEADS 16
#define HDIM  64
#define CDIM  1024
#define MROWS (BATCH * T_SEQ)       // 4096
#define BH    (BATCH * HEADS)       // 32

// ---------------------------------------------------------------------------
// Scratch
// ---------------------------------------------------------------------------
__device__ float g_qkv[MROWS * 3 * CDIM];
__device__ __nv_bfloat16 g_xbh[MROWS * CDIM],    g_xbl[MROWS * CDIM];
__device__ __nv_bfloat16 g_wbh[3 * CDIM * CDIM], g_wbl[3 * CDIM * CDIM];
__device__ __nv_bfloat16 g_obh[CDIM * CDIM],     g_obl[CDIM * CDIM];
__device__ __nv_bfloat16 g_abh[MROWS * CDIM],    g_abl[MROWS * CDIM];
__device__ __nv_bfloat16 g_qbh[BH * T_SEQ * HDIM], g_qbl[BH * T_SEQ * HDIM];
__device__ __nv_bfloat16 g_kbh[BH * T_SEQ * HDIM], g_kbl[BH * T_SEQ * HDIM];
__device__ __nv_bfloat16 g_vth[BH * HDIM * T_SEQ], g_vtl[BH * HDIM * T_SEQ];

// ---------------------------------------------------------------------------
// Helpers
// ---------------------------------------------------------------------------
__device__ __forceinline__ uint32_t smem_to_u32(const void* smem_ptr) {
    uint32_t addr;
    asm("{ .reg .u64 tmp; cvta.to.shared.u64 tmp, %1; cvt.u32.u64 %0, tmp; }"
        : "=r"(addr) : "l"(smem_ptr));
    return addr;
}

__device__ __forceinline__ void cp16(uint32_t dst, const void* src) {
    asm volatile("cp.async.cg.shared.global [%0], [%1], 16;\n" :: "r"(dst), "l"(src));
}

// ldmatrix x4: loads 4 8x8 b16 matrices; lane L supplies the row address
// computed by the caller.
__device__ __forceinline__ void ldm_x4(uint32_t& r0, uint32_t& r1,
                                       uint32_t& r2, uint32_t& r3, uint32_t a) {
    asm volatile("ldmatrix.sync.aligned.m8n8.x4.shared.b16 {%0,%1,%2,%3}, [%4];"
        : "=r"(r0), "=r"(r1), "=r"(r2), "=r"(r3) : "r"(a));
}

// mma.sync m16n8k16 bf16
__device__ __forceinline__ void mma_bf16(float* d, const uint32_t* a, const uint32_t* b) {
    asm volatile(
        "mma.sync.aligned.m16n8k16.row.col.f32.bf16.bf16.f32 "
        "{%0,%1,%2,%3}, {%4,%5,%6,%7}, {%8,%9}, {%0,%1,%2,%3};"
        : "+f"(d[0]), "+f"(d[1]), "+f"(d[2]), "+f"(d[3])
        : "r"(a[0]), "r"(a[1]), "r"(a[2]), "r"(a[3]), "r"(b[0]), "r"(b[1]));
}

// Split two fp32 into packed bf16x2 hi and lo (lo = residual)
__device__ __forceinline__ void split2(float v0, float v1, uint32_t& hi, uint32_t& lo) {
    __nv_bfloat16 h0 = __float2bfloat16(v0), h1 = __float2bfloat16(v1);
    float r0 = v0 - __bfloat162float(h0);
    float r1 = v1 - __bfloat162float(h1);
    __nv_bfloat16 l0 = __float2bfloat16(r0), l1 = __float2bfloat16(r1);
    hi = ((uint32_t)__bfloat16_as_ushort(h1) << 16) | __bfloat16_as_ushort(h0);
    lo = ((uint32_t)__bfloat16_as_ushort(l1) << 16) | __bfloat16_as_ushort(l0);
}

// ---------------------------------------------------------------------------
// fp32 -> (bf16 hi, bf16 lo) split
// ---------------------------------------------------------------------------
__global__ void split_bf16(const float* __restrict__ in,
                           __nv_bfloat16* __restrict__ hi, __nv_bfloat16* __restrict__ lo)
{
    int i = blockIdx.x * blockDim.x + threadIdx.x;
    float4 v = ((const float4*)in)[i];
    uint32_t h0, l0, h1, l1;
    split2(v.x, v.y, h0, l0);
    split2(v.z, v.w, h1, l1);
    ((uint2*)hi)[i] = make_uint2(h0, h1);
    ((uint2*)lo)[i] = make_uint2(l0, l1);
}

// ---------------------------------------------------------------------------
// bf16x3 GEMM (NT) with ldmatrix fragments + 3-stage cp.async
// ---------------------------------------------------------------------------
#define KT 32
#define BSTRIDE 80
#define BARR (128 * BSTRIDE)              // 10240
#define BSTAGE (4 * BARR)                 // 40960
#define GSTG 3
#define GEMM_SMEM (GSTG * BSTAGE)         // 122880

__global__ __launch_bounds__(256, 1)
void gemm_bf16x3(const __nv_bfloat16* __restrict__ Ahi, const __nv_bfloat16* __restrict__ Alo,
                 const __nv_bfloat16* __restrict__ Bhi, const __nv_bfloat16* __restrict__ Blo,
                 float* __restrict__ C, const float* __restrict__ bias,
                 int M, int N, int K)
{
    extern __shared__ char smem[];
    const uint32_t sbase = smem_to_u32(smem);
    const int tid  = threadIdx.x;
    const int wid  = tid >> 5;
    const int lane = tid & 31;
    const int wm   = wid & 3;
    const int wn   = wid >> 2;
    const int m0 = blockIdx.y * 128;
    const int n0 = blockIdx.x * 128;
    const int NKT = K / KT;
    const int frow = lane >> 2;
    const int fcol = lane & 3;
    // ldmatrix lane-address component (same formula for A and B fragments)
    const uint32_t lrow = (lane & 15);
    const uint32_t lcol16 = (lane >> 4) * 16;

    auto load_stage = [&](int s, int kt) {
        const int k0 = kt * KT;
        uint32_t st = sbase + s * BSTAGE;
        #pragma unroll
        for (int i = 0; i < 8; i++) {
            int idx = i * 256 + tid;
            int arr = idx >> 9;
            int rem = idx & 511;
            int r = rem >> 2, ch = rem & 3;
            uint32_t dst = st + arr * BARR + r * BSTRIDE + ch * 16;
            const __nv_bfloat16* src = (arr == 0) ? Ahi : (arr == 1) ? Alo
                                      : (arr == 2) ? Bhi : Blo;
            int rowg = ((arr < 2) ? m0 : n0) + r;
            cp16(dst, src + (size_t)rowg * K + k0 + ch * 8);
        }
        asm volatile("cp.async.commit_group;\n" ::: "memory");
    };

    load_stage(0, 0);
    load_stage(1, 1);
    load_stage(2, 2);

    float acc[2][8][4];
    #pragma unroll
    for (int mt = 0; mt < 2; mt++)
        #pragma unroll
        for (int nt = 0; nt < 8; nt++)
            #pragma unroll
            for (int j = 0; j < 4; j++) acc[mt][nt][j] = 0.f;

    for (int kt = 0; kt < NKT; kt++) {
        int s = kt % GSTG;
        asm volatile("cp.async.wait_group 2;\n" ::: "memory");
        __syncthreads();

        uint32_t Ah = sbase + s * BSTAGE;
        uint32_t Al = Ah + BARR;
        uint32_t Bh = Ah + 2 * BARR;
        uint32_t Bl = Ah + 3 * BARR;

        #pragma unroll
        for (int kk = 0; kk < 2; kk++) {
            const uint32_t kb = kk * 32 + lcol16;
            uint32_t ah[2][4], al[2][4];
            #pragma unroll
            for (int mt = 0; mt < 2; mt++) {
                uint32_t ra = (wm * 32 + mt * 16 + lrow) * BSTRIDE + kb;
                ldm_x4(ah[mt][0], ah[mt][1], ah[mt][2], ah[mt][3], Ah + ra);
                ldm_x4(al[mt][0], al[mt][1], al[mt][2], al[mt][3], Al + ra);
            }
            uint32_t bh[8][2], bl[8][2];
            #pragma unroll
            for (int ntp = 0; ntp < 4; ntp++) {
                uint32_t rb = (wn * 64 + ntp * 16 + lrow) * BSTRIDE + kb;
                ldm_x4(bh[2*ntp][0], bh[2*ntp+1][0], bh[2*ntp][1], bh[2*ntp+1][1], Bh + rb);
                ldm_x4(bl[2*ntp][0], bl[2*ntp+1][0], bl[2*ntp][1], bl[2*ntp+1][1], Bl + rb);
            }
            #pragma unroll
            for (int v = 0; v < 3; v++)
                #pragma unroll
                for (int mt = 0; mt < 2; mt++)
                    #pragma unroll
                    for (int nt = 0; nt < 8; nt++)
                        mma_bf16(acc[mt][nt],
                                 (v == 2) ? al[mt] : ah[mt],
                                 (v == 1) ? bl[nt] : bh[nt]);
        }

        __syncthreads();
        if (kt + GSTG < NKT) load_stage(s, kt + GSTG);
        else asm volatile("cp.async.commit_group;\n" ::: "memory");
    }

    #pragma unroll
    for (int mt = 0; mt < 2; mt++) {
        #pragma unroll
        for (int nt = 0; nt < 8; nt++) {
            int rg = m0 + wm * 32 + mt * 16 + frow;
            int cg = n0 + wn * 64 + nt * 8 + fcol * 2;
            float b0 = 0.f, b1 = 0.f;
            if (bias) { b0 = bias[cg]; b1 = bias[cg + 1]; }
            float2 v0 = make_float2(acc[mt][nt][0] + b0, acc[mt][nt][1] + b1);
            float2 v1 = make_float2(acc[mt][nt][2] + b0, acc[mt][nt][3] + b1);
            *(float2*)&C[(size_t)rg * N + cg]       = v0;
            *(float2*)&C[(size_t)(rg + 8) * N + cg] = v1;
        }
    }
}

// ---------------------------------------------------------------------------
// RoPE + bf16 hi/lo split
// ---------------------------------------------------------------------------
__global__ void rope_bsplit(const float* __restrict__ qkv,
                            __nv_bfloat16* __restrict__ qh, __nv_bfloat16* __restrict__ ql,
                            __nv_bfloat16* __restrict__ kh, __nv_bfloat16* __restrict__ kl)
{
    int idx = blockIdx.x * blockDim.x + threadIdx.x;
    int d   = idx & 31;
    int row = idx >> 5;
    int t   = row & (T_SEQ - 1);
    int bh  = row >> 11;
    int h   = bh & (HEADS - 1);
    int b   = bh >> 4;

    const float* base = qkv + (size_t)(b * T_SEQ + t) * (3 * CDIM) + h * HDIM;
    float q0 = base[d],        q1 = base[d + 32];
    float k0 = base[CDIM + d], k1 = base[CDIM + d + 32];

    float inv = (float)pow(10000.0, -(double)d / 32.0);
    float ang = (float)t * inv;
    float sv, cv;
    sincosf(ang, &sv, &cv);

    float qr0 = (q0 * cv - q1 * sv) * 0.125f;
    float qr1 = (q1 * cv + q0 * sv) * 0.125f;
    float kr0 = k0 * cv - k1 * sv;
    float kr1 = k1 * cv + k0 * sv;

    size_t o = (size_t)row * HDIM;
    __nv_bfloat16 hh;
    hh = __float2bfloat16(qr0); qh[o + d]      = hh; ql[o + d]      = __float2bfloat16(qr0 - __bfloat162float(hh));
    hh = __float2bfloat16(qr1); qh[o + d + 32] = hh; ql[o + d + 32] = __float2bfloat16(qr1 - __bfloat162float(hh));
    hh = __float2bfloat16(kr0); kh[o + d]      = hh; kl[o + d]      = __float2bfloat16(kr0 - __bfloat162float(hh));
    hh = __float2bfloat16(kr1); kh[o + d + 32] = hh; kl[o + d + 32] = __float2bfloat16(kr1 - __bfloat162float(hh));
}

// ---------------------------------------------------------------------------
// V split + transpose -> vt[bh, d, t]
// ---------------------------------------------------------------------------
__global__ void vsplit_t(const float* __restrict__ qkv,
                         __nv_bfloat16* __restrict__ vth, __nv_bfloat16* __restrict__ vtl)
{
    __shared__ float s[64 * 65];
    int tid = threadIdx.x;
    int bh = blockIdx.y, kt = blockIdx.x;
    int b = bh >> 4, h = bh & 15;

    #pragma unroll
    for (int i = 0; i < 4; i++) {
        int idx = i * 256 + tid;
        int tr = idx >> 4, c4 = idx & 15;
        float4 v = *(const float4*)&qkv[(size_t)(b * T_SEQ + kt * 64 + tr) * (3 * CDIM)
                                        + 2 * CDIM + h * HDIM + c4 * 4];
        s[tr * 65 + c4 * 4 + 0] = v.x;
        s[tr * 65 + c4 * 4 + 1] = v.y;
        s[tr * 65 + c4 * 4 + 2] = v.z;
        s[tr * 65 + c4 * 4 + 3] = v.w;
    }
    __syncthreads();

    #pragma unroll
    for (int i = 0; i < 8; i++) {
        int idx = i * 256 + tid;
        int d = idx >> 5, tp = idx & 31;
        float f0 = s[(2 * tp) * 65 + d];
        float f1 = s[(2 * tp + 1) * 65 + d];
        uint32_t hi, lo;
        split2(f0, f1, hi, lo);
        size_t o = ((size_t)(bh * HDIM + d) * T_SEQ + kt * 64 + 2 * tp) >> 1;
        ((uint32_t*)vth)[o] = hi;
        ((uint32_t*)vtl)[o] = lo;
    }
}

// ---------------------------------------------------------------------------
// Tensor-core flash attention (bf16x3) with ldmatrix + 3-stage cp.async
// ---------------------------------------------------------------------------
#define FSTRIDE_B 144
#define FARR (64 * FSTRIDE_B)
#define FSTAGE (4 * FARR)
#define FSTG 3
#define FLASH_SMEM (FSTG * FSTAGE)        // 110592

__global__ __launch_bounds__(256, 1)
void flash_mma(const __nv_bfloat16* __restrict__ qh, const __nv_bfloat16* __restrict__ ql,
               const __nv_bfloat16* __restrict__ kh, const __nv_bfloat16* __restrict__ kl,
               const __nv_bfloat16* __restrict__ vth, const __nv_bfloat16* __restrict__ vtl,
               __nv_bfloat16* __restrict__ oh, __nv_bfloat16* __restrict__ ol)
{
    extern __shared__ char fsm[];
    const uint32_t sbase = smem_to_u32(fsm);
    const int tid  = threadIdx.x;
    const int wid  = tid >> 5;
    const int lane = tid & 31;
    const int frow = lane >> 2;
    const int fcol = lane & 3;
    const int qt = blockIdx.x, bh = blockIdx.y;
    const uint32_t lrow = (lane & 15);
    const uint32_t lcol16 = (lane >> 4) * 16;

    uint32_t aqh[4][4], aql[4][4];
    {
        const uint32_t* q32h = (const uint32_t*)(qh + ((size_t)bh * T_SEQ + qt * 128 + wid * 16) * HDIM);
        const uint32_t* q32l = (const uint32_t*)(ql + ((size_t)bh * T_SEQ + qt * 128 + wid * 16) * HDIM);
        #pragma unroll
        for (int kc = 0; kc < 4; kc++) {
            int c0 = kc * 8 + fcol;
            aqh[kc][0] = q32h[frow * 32 + c0];
            aqh[kc][1] = q32h[(frow + 8) * 32 + c0];
            aqh[kc][2] = q32h[frow * 32 + c0 + 4];
            aqh[kc][3] = q32h[(frow + 8) * 32 + c0 + 4];
            aql[kc][0] = q32l[frow * 32 + c0];
            aql[kc][1] = q32l[(frow + 8) * 32 + c0];
            aql[kc][2] = q32l[frow * 32 + c0 + 4];
            aql[kc][3] = q32l[(frow + 8) * 32 + c0 + 4];
        }
    }

    float m0 = -1e30f, m1 = -1e30f, l0 = 0.f, l1 = 0.f;
    float o[8][4];
    #pragma unroll
    for (int nt = 0; nt < 8; nt++)
        #pragma unroll
        for (int j = 0; j < 4; j++) o[nt][j] = 0.f;

    const __nv_bfloat16* khg = kh  + (size_t)bh * T_SEQ * HDIM;
    const __nv_bfloat16* klg = kl  + (size_t)bh * T_SEQ * HDIM;
    const __nv_bfloat16* vhg = vth + (size_t)bh * HDIM * T_SEQ;
    const __nv_bfloat16* vlg = vtl + (size_t)bh * HDIM * T_SEQ;

    auto load_stage = [&](int s, int kt) {
        uint32_t st = sbase + s * FSTAGE;
        #pragma unroll
        for (int i = 0; i < 8; i++) {
            int idx = i * 256 + tid;
            int arr = idx >> 9;
            int rem = idx & 511;
            int r = rem >> 3, ch = rem & 7;
            uint32_t dst = st + arr * FARR + r * FSTRIDE_B + ch * 16;
            const __nv_bfloat16* src;
            if      (arr == 0) src = khg + (size_t)(kt * 64 + r) * HDIM + ch * 8;
            else if (arr == 1) src = klg + (size_t)(kt * 64 + r) * HDIM + ch * 8;
            else if (arr == 2) src = vhg + (size_t)r * T_SEQ + kt * 64 + ch * 8;
            else               src = vlg + (size_t)r * T_SEQ + kt * 64 + ch * 8;
            cp16(dst, src);
        }
        asm volatile("cp.async.commit_group;\n" ::: "memory");
    };

    load_stage(0, 0);
    load_stage(1, 1);
    load_stage(2, 2);

    const int NKT = T_SEQ / 64;
    for (int kt = 0; kt < NKT; kt++) {
        int s = kt % FSTG;
        asm volatile("cp.async.wait_group 2;\n" ::: "memory");
        __syncthreads();

        uint32_t Kh = sbase + s * FSTAGE;
        uint32_t Kl = Kh + FARR;
        uint32_t Vh = Kh + 2 * FARR;
        uint32_t Vl = Kh + 3 * FARR;

        float sa[8][4];
        #pragma unroll
        for (int nt = 0; nt < 8; nt++)
            #pragma unroll
            for (int j = 0; j < 4; j++) sa[nt][j] = 0.f;

        #pragma unroll
        for (int kc = 0; kc < 4; kc++) {
            const uint32_t kb = kc * 32 + lcol16;
            uint32_t kbh[8][2], kbl[8][2];
            #pragma unroll
            for (int ntp = 0; ntp < 4; ntp++) {
                uint32_t ad = (ntp * 16 + lrow) * FSTRIDE_B + kb;
                ldm_x4(kbh[2*ntp][0], kbh[2*ntp+1][0], kbh[2*ntp][1], kbh[2*ntp+1][1], Kh + ad);
                ldm_x4(kbl[2*ntp][0], kbl[2*ntp+1][0], kbl[2*ntp][1], kbl[2*ntp+1][1], Kl + ad);
            }
            #pragma unroll
            for (int nt = 0; nt < 8; nt++) mma_bf16(sa[nt], aqh[kc], kbh[nt]);
            #pragma unroll
            for (int nt = 0; nt < 8; nt++) mma_bf16(sa[nt], aqh[kc], kbl[nt]);
            #pragma unroll
            for (int nt = 0; nt < 8; nt++) mma_bf16(sa[nt], aql[kc], kbh[nt]);
        }

        float mx0 = sa[0][0], mx1 = sa[0][2];
        #pragma unroll
        for (int nt = 0; nt < 8; nt++) {
            mx0 = fmaxf(mx0, fmaxf(sa[nt][0], sa[nt][1]));
            mx1 = fmaxf(mx1, fmaxf(sa[nt][2], sa[nt][3]));
        }
        mx0 = fmaxf(mx0, __shfl_xor_sync(0xffffffffu, mx0, 1));
        mx0 = fmaxf(mx0, __shfl_xor_sync(0xffffffffu, mx0, 2));
        mx1 = fmaxf(mx1, __shfl_xor_sync(0xffffffffu, mx1, 1));
        mx1 = fmaxf(mx1, __shfl_xor_sync(0xffffffffu, mx1, 2));

        float nm0 = fmaxf(m0, mx0), nm1 = fmaxf(m1, mx1);
        float c0 = __expf(m0 - nm0), c1 = __expf(m1 - nm1);
        m0 = nm0; m1 = nm1;

        float rs0 = 0.f, rs1 = 0.f;
        #pragma unroll
        for (int nt = 0; nt < 8; nt++) {
            sa[nt][0] = __expf(sa[nt][0] - m0);
            sa[nt][1] = __expf(sa[nt][1] - m0);
            sa[nt][2] = __expf(sa[nt][2] - m1);
            sa[nt][3] = __expf(sa[nt][3] - m1);
            rs0 += sa[nt][0] + sa[nt][1];
            rs1 += sa[nt][2] + sa[nt][3];
        }
        rs0 += __shfl_xor_sync(0xffffffffu, rs0, 1);
        rs0 += __shfl_xor_sync(0xffffffffu, rs0, 2);
        rs1 += __shfl_xor_sync(0xffffffffu, rs1, 1);
        rs1 += __shfl_xor_sync(0xffffffffu, rs1, 2);
        l0 = l0 * c0 + rs0;
        l1 = l1 * c1 + rs1;
        #pragma unroll
        for (int nt = 0; nt < 8; nt++) {
            o[nt][0] *= c0; o[nt][1] *= c0;
            o[nt][2] *= c1; o[nt][3] *= c1;
        }

        #pragma unroll
        for (int kc = 0; kc < 4; kc++) {
            uint32_t pah[4], pal[4];
            split2(sa[2 * kc][0],     sa[2 * kc][1],     pah[0], pal[0]);
            split2(sa[2 * kc][2],     sa[2 * kc][3],     pah[1], pal[1]);
            split2(sa[2 * kc + 1][0], sa[2 * kc + 1][1], pah[2], pal[2]);
            split2(sa[2 * kc + 1][2], sa[2 * kc + 1][3], pah[3], pal[3]);

            const uint32_t kb = kc * 32 + lcol16;
            uint32_t vbh[8][2], vbl[8][2];
            #pragma unroll
            for (int ntp = 0; ntp < 4; ntp++) {
                uint32_t ad = (ntp * 16 + lrow) * FSTRIDE_B + kb;
                ldm_x4(vbh[2*ntp][0], vbh[2*ntp+1][0], vbh[2*ntp][1], vbh[2*ntp+1][1], Vh + ad);
                ldm_x4(vbl[2*ntp][0], vbl[2*ntp+1][0], vbl[2*ntp][1], vbl[2*ntp+1][1], Vl + ad);
            }
            #pragma unroll
            for (int nt = 0; nt < 8; nt++) mma_bf16(o[nt], pah, vbh[nt]);
            #pragma unroll
            for (int nt = 0; nt < 8; nt++) mma_bf16(o[nt], pah, vbl[nt]);
            #pragma unroll
            for (int nt = 0; nt < 8; nt++) mma_bf16(o[nt], pal, vbh[nt]);
        }

        __syncthreads();
        if (kt + FSTG < NKT) load_stage(s, kt + FSTG);
        else asm volatile("cp.async.commit_group;\n" ::: "memory");
    }

    float i0 = 1.f / l0, i1 = 1.f / l1;
    size_t ob = ((size_t)(bh >> 4) * T_SEQ + qt * 128 + wid * 16) * CDIM + (bh & 15) * HDIM;
    #pragma unroll
    for (int nt = 0; nt < 8; nt++) {
        int cg = nt * 8 + 2 * fcol;
        uint32_t h0, lo0, h1, lo1;
        split2(o[nt][0] * i0, o[nt][1] * i0, h0, lo0);
        split2(o[nt][2] * i1, o[nt][3] * i1, h1, lo1);
        size_t p0 = (ob + (size_t)frow * CDIM + cg) >> 1;
        size_t p1 = (ob + (size_t)(frow + 8) * CDIM + cg) >> 1;
        ((uint32_t*)oh)[p0] = h0;
        ((uint32_t*)ol)[p0] = lo0;
        ((uint32_t*)oh)[p1] = h1;
        ((uint32_t*)ol)[p1] = lo1;
    }
}

// ---------------------------------------------------------------------------
// Launch
// ---------------------------------------------------------------------------
extern "C" void kernel_launch(void* const* d_in, const int* in_sizes, int n_in,
                              void* d_out, int out_size)
{
    const float* x    = (const float*)d_in[0];
    const float* Wqkv = (const float*)d_in[1];
    const float* Wout = (const float*)d_in[2];
    const float* bout = (const float*)d_in[3];
    float* out = (float*)d_out;

    void *pqkv, *pxbh, *pxbl, *pwbh, *pwbl, *pobh, *pobl, *pabh, *pabl;
    void *pqbh, *pqbl, *pkbh, *pkbl, *pvth, *pvtl;
    cudaGetSymbolAddress(&pqkv, g_qkv);
    cudaGetSymbolAddress(&pxbh, g_xbh);
    cudaGetSymbolAddress(&pxbl, g_xbl);
    cudaGetSymbolAddress(&pwbh, g_wbh);
    cudaGetSymbolAddress(&pwbl, g_wbl);
    cudaGetSymbolAddress(&pobh, g_obh);
    cudaGetSymbolAddress(&pobl, g_obl);
    cudaGetSymbolAddress(&pabh, g_abh);
    cudaGetSymbolAddress(&pabl, g_abl);
    cudaGetSymbolAddress(&pqbh, g_qbh);
    cudaGetSymbolAddress(&pqbl, g_qbl);
    cudaGetSymbolAddress(&pkbh, g_kbh);
    cudaGetSymbolAddress(&pkbl, g_kbl);
    cudaGetSymbolAddress(&pvth, g_vth);
    cudaGetSymbolAddress(&pvtl, g_vtl);
    float* qkv = (float*)pqkv;

    cudaFuncSetAttribute(gemm_bf16x3,
                         cudaFuncAttributeMaxDynamicSharedMemorySize, GEMM_SMEM);
    cudaFuncSetAttribute(flash_mma,
                         cudaFuncAttributeMaxDynamicSharedMemorySize, FLASH_SMEM);

    split_bf16<<<(MROWS * CDIM / 4) / 256, 256>>>(x, (__nv_bfloat16*)pxbh, (__nv_bfloat16*)pxbl);
    split_bf16<<<(3 * CDIM * CDIM / 4) / 256, 256>>>(Wqkv, (__nv_bfloat16*)pwbh, (__nv_bfloat16*)pwbl);
    split_bf16<<<(CDIM * CDIM / 4) / 256, 256>>>(Wout, (__nv_bfloat16*)pobh, (__nv_bfloat16*)pobl);

    gemm_bf16x3<<<dim3(3 * CDIM / 128, MROWS / 128), 256, GEMM_SMEM>>>(
        (const __nv_bfloat16*)pxbh, (const __nv_bfloat16*)pxbl,
        (const __nv_bfloat16*)pwbh, (const __nv_bfloat16*)pwbl,
        qkv, nullptr, MROWS, 3 * CDIM, CDIM);

    rope_bsplit<<<(BH * T_SEQ * 32) / 256, 256>>>(
        qkv, (__nv_bfloat16*)pqbh, (__nv_bfloat16*)pqbl,
        (__nv_bfloat16*)pkbh, (__nv_bfloat16*)pkbl);
    vsplit_t<<<dim3(T_SEQ / 64, BH), 256>>>(
        qkv, (__nv_bfloat16*)pvth, (__nv_bfloat16*)pvtl);

    flash_mma<<<dim3(T_SEQ / 128, BH), 256, FLASH_SMEM>>>(
        (const __nv_bfloat16*)pqbh, (const __nv_bfloat16*)pqbl,
        (const __nv_bfloat16*)pkbh, (const __nv_bfloat16*)pkbl,
        (const __nv_bfloat16*)pvth, (const __nv_bfloat16*)pvtl,
        (__nv_bfloat16*)pabh, (__nv_bfloat16*)pabl);

    gemm_bf16x3<<<dim3(CDIM / 128, MROWS / 128), 256, GEMM_SMEM>>>(
        (const __nv_bfloat16*)pabh, (const __nv_bfloat16*)pabl,
        (const __nv_bfloat16*)pobh, (const __nv_bfloat16*)pobl,
        out, bout, MROWS, CDIM, CDIM);
}

// round 8
// speedup vs baseline: 1.1335x; 1.1335x over previous
#include <cuda_runtime.h>
#include <cuda_bf16.h>
#include <math.h>
#include <stdint.h>

// Problem constants
#define T_SEQ 2048
#define BATCH 2
#define HEADS 16
#define HDIM  64
#define CDIM  1024
#define MROWS (BATCH * T_SEQ)       // 4096
#define BH    (BATCH * HEADS)       // 32

// ---------------------------------------------------------------------------
// Scratch
// ---------------------------------------------------------------------------
__device__ float g_qkv[MROWS * 3 * CDIM];
__device__ __nv_bfloat16 g_xbh[MROWS * CDIM],    g_xbl[MROWS * CDIM];
__device__ __nv_bfloat16 g_wbh[3 * CDIM * CDIM], g_wbl[3 * CDIM * CDIM];
__device__ __nv_bfloat16 g_obh[CDIM * CDIM],     g_obl[CDIM * CDIM];
__device__ __nv_bfloat16 g_abh[MROWS * CDIM],    g_abl[MROWS * CDIM];
__device__ __nv_bfloat16 g_qbh[BH * T_SEQ * HDIM], g_qbl[BH * T_SEQ * HDIM];
__device__ __nv_bfloat16 g_kbh[BH * T_SEQ * HDIM], g_kbl[BH * T_SEQ * HDIM];
__device__ __nv_bfloat16 g_vth[BH * HDIM * T_SEQ], g_vtl[BH * HDIM * T_SEQ];

// ---------------------------------------------------------------------------
// Helpers
// ---------------------------------------------------------------------------
__device__ __forceinline__ uint32_t smem_to_u32(const void* smem_ptr) {
    uint32_t addr;
    asm("{ .reg .u64 tmp; cvta.to.shared.u64 tmp, %1; cvt.u32.u64 %0, tmp; }"
        : "=r"(addr) : "l"(smem_ptr));
    return addr;
}

__device__ __forceinline__ void cp16(uint32_t dst, const void* src) {
    asm volatile("cp.async.cg.shared.global [%0], [%1], 16;\n" :: "r"(dst), "l"(src));
}

__device__ __forceinline__ uint32_t lds32(uint32_t a) {
    uint32_t v;
    asm volatile("ld.shared.b32 %0, [%1];" : "=r"(v) : "r"(a));
    return v;
}

// mma.sync m16n8k16 bf16
__device__ __forceinline__ void mma_bf16(float* d, const uint32_t* a, const uint32_t* b) {
    asm volatile(
        "mma.sync.aligned.m16n8k16.row.col.f32.bf16.bf16.f32 "
        "{%0,%1,%2,%3}, {%4,%5,%6,%7}, {%8,%9}, {%0,%1,%2,%3};"
        : "+f"(d[0]), "+f"(d[1]), "+f"(d[2]), "+f"(d[3])
        : "r"(a[0]), "r"(a[1]), "r"(a[2]), "r"(a[3]), "r"(b[0]), "r"(b[1]));
}

// Split two fp32 into packed bf16x2 hi and lo (lo = residual)
__device__ __forceinline__ void split2(float v0, float v1, uint32_t& hi, uint32_t& lo) {
    __nv_bfloat16 h0 = __float2bfloat16(v0), h1 = __float2bfloat16(v1);
    float r0 = v0 - __bfloat162float(h0);
    float r1 = v1 - __bfloat162float(h1);
    __nv_bfloat16 l0 = __float2bfloat16(r0), l1 = __float2bfloat16(r1);
    hi = ((uint32_t)__bfloat16_as_ushort(h1) << 16) | __bfloat16_as_ushort(h0);
    lo = ((uint32_t)__bfloat16_as_ushort(l1) << 16) | __bfloat16_as_ushort(l0);
}

// ---------------------------------------------------------------------------
// fp32 -> (bf16 hi, bf16 lo) split
// ---------------------------------------------------------------------------
__global__ void split_bf16(const float* __restrict__ in,
                           __nv_bfloat16* __restrict__ hi, __nv_bfloat16* __restrict__ lo)
{
    int i = blockIdx.x * blockDim.x + threadIdx.x;
    float4 v = ((const float4*)in)[i];
    uint32_t h0, l0, h1, l1;
    split2(v.x, v.y, h0, l0);
    split2(v.z, v.w, h1, l1);
    ((uint2*)hi)[i] = make_uint2(h0, h1);
    ((uint2*)lo)[i] = make_uint2(l0, l1);
}

// ---------------------------------------------------------------------------
// bf16x3 GEMM (NT): CTA tile 128x64, 128 threads (4 warps, 32x64 each),
// K-tile 32, 2-stage cp.async, plain LDS fragments.
// Small CTA -> multiple CTAs/SM for latency hiding.
// ---------------------------------------------------------------------------
#define KT 32
#define BSTRIDE 80                        // bytes per smem row
#define A_BYTES (128 * BSTRIDE)           // 10240
#define B_BYTES (64 * BSTRIDE)            // 5120
#define GSTAGE (2 * A_BYTES + 2 * B_BYTES)  // 30720
#define GEMM_SMEM (2 * GSTAGE)            // 61440

__global__ __launch_bounds__(128, 1)
void gemm_bf16x3(const __nv_bfloat16* __restrict__ Ahi, const __nv_bfloat16* __restrict__ Alo,
                 const __nv_bfloat16* __restrict__ Bhi, const __nv_bfloat16* __restrict__ Blo,
                 float* __restrict__ C, const float* __restrict__ bias,
                 int M, int N, int K)
{
    extern __shared__ char smem[];
    const uint32_t sbase = smem_to_u32(smem);
    const int tid  = threadIdx.x;
    const int wid  = tid >> 5;
    const int lane = tid & 31;
    const int m0 = blockIdx.y * 128;
    const int n0 = blockIdx.x * 64;
    const int NKT = K / KT;
    const int frow = lane >> 2;
    const int fcol = lane & 3;

    auto load_stage = [&](int s, int kt) {
        const int k0 = kt * KT;
        uint32_t st = sbase + s * GSTAGE;
        #pragma unroll
        for (int i = 0; i < 12; i++) {
            int idx = i * 128 + tid;
            int arr, rem;
            uint32_t abase;
            if      (idx < 512)  { arr = 0; rem = idx;        abase = 0; }
            else if (idx < 1024) { arr = 1; rem = idx - 512;  abase = A_BYTES; }
            else if (idx < 1280) { arr = 2; rem = idx - 1024; abase = 2 * A_BYTES; }
            else                 { arr = 3; rem = idx - 1280; abase = 2 * A_BYTES + B_BYTES; }
            int r = rem >> 2, ch = rem & 3;
            uint32_t dst = st + abase + r * BSTRIDE + ch * 16;
            const __nv_bfloat16* src = (arr == 0) ? Ahi : (arr == 1) ? Alo
                                      : (arr == 2) ? Bhi : Blo;
            int rowg = ((arr < 2) ? m0 : n0) + r;
            cp16(dst, src + (size_t)rowg * K + k0 + ch * 8);
        }
        asm volatile("cp.async.commit_group;\n" ::: "memory");
    };

    load_stage(0, 0);
    load_stage(1, 1);

    float acc[2][8][4];
    #pragma unroll
    for (int mt = 0; mt < 2; mt++)
        #pragma unroll
        for (int nt = 0; nt < 8; nt++)
            #pragma unroll
            for (int j = 0; j < 4; j++) acc[mt][nt][j] = 0.f;

    for (int kt = 0; kt < NKT; kt++) {
        int s = kt & 1;
        asm volatile("cp.async.wait_group 1;\n" ::: "memory");
        __syncthreads();

        uint32_t Ah = sbase + s * GSTAGE;
        uint32_t Al = Ah + A_BYTES;
        uint32_t Bh = Ah + 2 * A_BYTES;
        uint32_t Bl = Bh + B_BYTES;

        #pragma unroll
        for (int kk = 0; kk < 2; kk++) {
            const uint32_t kb = kk * 32 + 4 * fcol;
            uint32_t ah[2][4], al[2][4];
            #pragma unroll
            for (int mt = 0; mt < 2; mt++) {
                uint32_t ra = (wid * 32 + mt * 16 + frow) * BSTRIDE + kb;
                ah[mt][0] = lds32(Ah + ra);
                ah[mt][1] = lds32(Ah + ra + 8 * BSTRIDE);
                ah[mt][2] = lds32(Ah + ra + 16);
                ah[mt][3] = lds32(Ah + ra + 8 * BSTRIDE + 16);
                al[mt][0] = lds32(Al + ra);
                al[mt][1] = lds32(Al + ra + 8 * BSTRIDE);
                al[mt][2] = lds32(Al + ra + 16);
                al[mt][3] = lds32(Al + ra + 8 * BSTRIDE + 16);
            }
            uint32_t bh[8][2], bl[8][2];
            #pragma unroll
            for (int nt = 0; nt < 8; nt++) {
                uint32_t rb = (nt * 8 + frow) * BSTRIDE + kb;
                bh[nt][0] = lds32(Bh + rb);
                bh[nt][1] = lds32(Bh + rb + 16);
                bl[nt][0] = lds32(Bl + rb);
                bl[nt][1] = lds32(Bl + rb + 16);
            }
            #pragma unroll
            for (int v = 0; v < 3; v++)
                #pragma unroll
                for (int mt = 0; mt < 2; mt++)
                    #pragma unroll
                    for (int nt = 0; nt < 8; nt++)
                        mma_bf16(acc[mt][nt],
                                 (v == 2) ? al[mt] : ah[mt],
                                 (v == 1) ? bl[nt] : bh[nt]);
        }

        __syncthreads();
        if (kt + 2 < NKT) load_stage(s, kt + 2);
        else asm volatile("cp.async.commit_group;\n" ::: "memory");
    }

    #pragma unroll
    for (int mt = 0; mt < 2; mt++) {
        #pragma unroll
        for (int nt = 0; nt < 8; nt++) {
            int rg = m0 + wid * 32 + mt * 16 + frow;
            int cg = n0 + nt * 8 + fcol * 2;
            float b0 = 0.f, b1 = 0.f;
            if (bias) { b0 = bias[cg]; b1 = bias[cg + 1]; }
            float2 v0 = make_float2(acc[mt][nt][0] + b0, acc[mt][nt][1] + b1);
            float2 v1 = make_float2(acc[mt][nt][2] + b0, acc[mt][nt][3] + b1);
            *(float2*)&C[(size_t)rg * N + cg]       = v0;
            *(float2*)&C[(size_t)(rg + 8) * N + cg] = v1;
        }
    }
}

// ---------------------------------------------------------------------------
// RoPE + bf16 hi/lo split
// ---------------------------------------------------------------------------
__global__ void rope_bsplit(const float* __restrict__ qkv,
                            __nv_bfloat16* __restrict__ qh, __nv_bfloat16* __restrict__ ql,
                            __nv_bfloat16* __restrict__ kh, __nv_bfloat16* __restrict__ kl)
{
    int idx = blockIdx.x * blockDim.x + threadIdx.x;
    int d   = idx & 31;
    int row = idx >> 5;
    int t   = row & (T_SEQ - 1);
    int bh  = row >> 11;
    int h   = bh & (HEADS - 1);
    int b   = bh >> 4;

    const float* base = qkv + (size_t)(b * T_SEQ + t) * (3 * CDIM) + h * HDIM;
    float q0 = base[d],        q1 = base[d + 32];
    float k0 = base[CDIM + d], k1 = base[CDIM + d + 32];

    float inv = (float)pow(10000.0, -(double)d / 32.0);
    float ang = (float)t * inv;
    float sv, cv;
    sincosf(ang, &sv, &cv);

    float qr0 = (q0 * cv - q1 * sv) * 0.125f;
    float qr1 = (q1 * cv + q0 * sv) * 0.125f;
    float kr0 = k0 * cv - k1 * sv;
    float kr1 = k1 * cv + k0 * sv;

    size_t o = (size_t)row * HDIM;
    __nv_bfloat16 hh;
    hh = __float2bfloat16(qr0); qh[o + d]      = hh; ql[o + d]      = __float2bfloat16(qr0 - __bfloat162float(hh));
    hh = __float2bfloat16(qr1); qh[o + d + 32] = hh; ql[o + d + 32] = __float2bfloat16(qr1 - __bfloat162float(hh));
    hh = __float2bfloat16(kr0); kh[o + d]      = hh; kl[o + d]      = __float2bfloat16(kr0 - __bfloat162float(hh));
    hh = __float2bfloat16(kr1); kh[o + d + 32] = hh; kl[o + d + 32] = __float2bfloat16(kr1 - __bfloat162float(hh));
}

// ---------------------------------------------------------------------------
// V split + transpose -> vt[bh, d, t]
// ---------------------------------------------------------------------------
__global__ void vsplit_t(const float* __restrict__ qkv,
                         __nv_bfloat16* __restrict__ vth, __nv_bfloat16* __restrict__ vtl)
{
    __shared__ float s[64 * 65];
    int tid = threadIdx.x;
    int bh = blockIdx.y, kt = blockIdx.x;
    int b = bh >> 4, h = bh & 15;

    #pragma unroll
    for (int i = 0; i < 4; i++) {
        int idx = i * 256 + tid;
        int tr = idx >> 4, c4 = idx & 15;
        float4 v = *(const float4*)&qkv[(size_t)(b * T_SEQ + kt * 64 + tr) * (3 * CDIM)
                                        + 2 * CDIM + h * HDIM + c4 * 4];
        s[tr * 65 + c4 * 4 + 0] = v.x;
        s[tr * 65 + c4 * 4 + 1] = v.y;
        s[tr * 65 + c4 * 4 + 2] = v.z;
        s[tr * 65 + c4 * 4 + 3] = v.w;
    }
    __syncthreads();

    #pragma unroll
    for (int i = 0; i < 8; i++) {
        int idx = i * 256 + tid;
        int d = idx >> 5, tp = idx & 31;
        float f0 = s[(2 * tp) * 65 + d];
        float f1 = s[(2 * tp + 1) * 65 + d];
        uint32_t hi, lo;
        split2(f0, f1, hi, lo);
        size_t o = ((size_t)(bh * HDIM + d) * T_SEQ + kt * 64 + 2 * tp) >> 1;
        ((uint32_t*)vth)[o] = hi;
        ((uint32_t*)vtl)[o] = lo;
    }
}

// ---------------------------------------------------------------------------
// Tensor-core flash attention (bf16x3 for BOTH QK^T and PV — R5 numerics)
// CTA: 64 q rows, 128 threads (4 warps, 16 rows each), 2-stage cp.async.
// ---------------------------------------------------------------------------
#define FSTRIDE_B 144
#define FARR (64 * FSTRIDE_B)
#define FSTAGE (4 * FARR)
#define FLASH_SMEM (2 * FSTAGE)           // 73728

__global__ __launch_bounds__(128, 1)
void flash_mma(const __nv_bfloat16* __restrict__ qh, const __nv_bfloat16* __restrict__ ql,
               const __nv_bfloat16* __restrict__ kh, const __nv_bfloat16* __restrict__ kl,
               const __nv_bfloat16* __restrict__ vth, const __nv_bfloat16* __restrict__ vtl,
               __nv_bfloat16* __restrict__ oh, __nv_bfloat16* __restrict__ ol)
{
    extern __shared__ char fsm[];
    const uint32_t sbase = smem_to_u32(fsm);
    const int tid  = threadIdx.x;
    const int wid  = tid >> 5;
    const int lane = tid & 31;
    const int frow = lane >> 2;
    const int fcol = lane & 3;
    const int qt = blockIdx.x, bh = blockIdx.y;

    uint32_t aqh[4][4], aql[4][4];
    {
        const uint32_t* q32h = (const uint32_t*)(qh + ((size_t)bh * T_SEQ + qt * 64 + wid * 16) * HDIM);
        const uint32_t* q32l = (const uint32_t*)(ql + ((size_t)bh * T_SEQ + qt * 64 + wid * 16) * HDIM);
        #pragma unroll
        for (int kc = 0; kc < 4; kc++) {
            int c0 = kc * 8 + fcol;
            aqh[kc][0] = q32h[frow * 32 + c0];
            aqh[kc][1] = q32h[(frow + 8) * 32 + c0];
            aqh[kc][2] = q32h[frow * 32 + c0 + 4];
            aqh[kc][3] = q32h[(frow + 8) * 32 + c0 + 4];
            aql[kc][0] = q32l[frow * 32 + c0];
            aql[kc][1] = q32l[(frow + 8) * 32 + c0];
            aql[kc][2] = q32l[frow * 32 + c0 + 4];
            aql[kc][3] = q32l[(frow + 8) * 32 + c0 + 4];
        }
    }

    float m0 = -1e30f, m1 = -1e30f, l0 = 0.f, l1 = 0.f;
    float o[8][4];
    #pragma unroll
    for (int nt = 0; nt < 8; nt++)
        #pragma unroll
        for (int j = 0; j < 4; j++) o[nt][j] = 0.f;

    const __nv_bfloat16* khg = kh  + (size_t)bh * T_SEQ * HDIM;
    const __nv_bfloat16* klg = kl  + (size_t)bh * T_SEQ * HDIM;
    const __nv_bfloat16* vhg = vth + (size_t)bh * HDIM * T_SEQ;
    const __nv_bfloat16* vlg = vtl + (size_t)bh * HDIM * T_SEQ;

    auto load_stage = [&](int s, int kt) {
        uint32_t st = sbase + s * FSTAGE;
        #pragma unroll
        for (int i = 0; i < 16; i++) {
            int idx = i * 128 + tid;
            int arr = idx >> 9;
            int rem = idx & 511;
            int r = rem >> 3, ch = rem & 7;
            uint32_t dst = st + arr * FARR + r * FSTRIDE_B + ch * 16;
            const __nv_bfloat16* src;
            if      (arr == 0) src = khg + (size_t)(kt * 64 + r) * HDIM + ch * 8;
            else if (arr == 1) src = klg + (size_t)(kt * 64 + r) * HDIM + ch * 8;
            else if (arr == 2) src = vhg + (size_t)r * T_SEQ + kt * 64 + ch * 8;
            else               src = vlg + (size_t)r * T_SEQ + kt * 64 + ch * 8;
            cp16(dst, src);
        }
        asm volatile("cp.async.commit_group;\n" ::: "memory");
    };

    load_stage(0, 0);
    load_stage(1, 1);

    const int NKT = T_SEQ / 64;
    for (int kt = 0; kt < NKT; kt++) {
        int s = kt & 1;
        asm volatile("cp.async.wait_group 1;\n" ::: "memory");
        __syncthreads();

        uint32_t Kh = sbase + s * FSTAGE;
        uint32_t Kl = Kh + FARR;
        uint32_t Vh = Kh + 2 * FARR;
        uint32_t Vl = Kh + 3 * FARR;

        float sa[8][4];
        #pragma unroll
        for (int nt = 0; nt < 8; nt++)
            #pragma unroll
            for (int j = 0; j < 4; j++) sa[nt][j] = 0.f;

        #pragma unroll
        for (int kc = 0; kc < 4; kc++) {
            uint32_t kbh[8][2], kbl[8][2];
            #pragma unroll
            for (int nt = 0; nt < 8; nt++) {
                uint32_t ad = (nt * 8 + frow) * FSTRIDE_B + (kc * 16 + 2 * fcol) * 2;
                kbh[nt][0] = lds32(Kh + ad);
                kbh[nt][1] = lds32(Kh + ad + 16);
                kbl[nt][0] = lds32(Kl + ad);
                kbl[nt][1] = lds32(Kl + ad + 16);
            }
            #pragma unroll
            for (int nt = 0; nt < 8; nt++) mma_bf16(sa[nt], aqh[kc], kbh[nt]);
            #pragma unroll
            for (int nt = 0; nt < 8; nt++) mma_bf16(sa[nt], aqh[kc], kbl[nt]);
            #pragma unroll
            for (int nt = 0; nt < 8; nt++) mma_bf16(sa[nt], aql[kc], kbh[nt]);
        }

        float mx0 = sa[0][0], mx1 = sa[0][2];
        #pragma unroll
        for (int nt = 0; nt < 8; nt++) {
            mx0 = fmaxf(mx0, fmaxf(sa[nt][0], sa[nt][1]));
            mx1 = fmaxf(mx1, fmaxf(sa[nt][2], sa[nt][3]));
        }
        mx0 = fmaxf(mx0, __shfl_xor_sync(0xffffffffu, mx0, 1));
        mx0 = fmaxf(mx0, __shfl_xor_sync(0xffffffffu, mx0, 2));
        mx1 = fmaxf(mx1, __shfl_xor_sync(0xffffffffu, mx1, 1));
        mx1 = fmaxf(mx1, __shfl_xor_sync(0xffffffffu, mx1, 2));

        float nm0 = fmaxf(m0, mx0), nm1 = fmaxf(m1, mx1);
        float c0 = __expf(m0 - nm0), c1 = __expf(m1 - nm1);
        m0 = nm0; m1 = nm1;

        float rs0 = 0.f, rs1 = 0.f;
        #pragma unroll
        for (int nt = 0; nt < 8; nt++) {
            sa[nt][0] = __expf(sa[nt][0] - m0);
            sa[nt][1] = __expf(sa[nt][1] - m0);
            sa[nt][2] = __expf(sa[nt][2] - m1);
            sa[nt][3] = __expf(sa[nt][3] - m1);
            rs0 += sa[nt][0] + sa[nt][1];
            rs1 += sa[nt][2] + sa[nt][3];
        }
        rs0 += __shfl_xor_sync(0xffffffffu, rs0, 1);
        rs0 += __shfl_xor_sync(0xffffffffu, rs0, 2);
        rs1 += __shfl_xor_sync(0xffffffffu, rs1, 1);
        rs1 += __shfl_xor_sync(0xffffffffu, rs1, 2);
        l0 = l0 * c0 + rs0;
        l1 = l1 * c1 + rs1;
        #pragma unroll
        for (int nt = 0; nt < 8; nt++) {
            o[nt][0] *= c0; o[nt][1] *= c0;
            o[nt][2] *= c1; o[nt][3] *= c1;
        }

        // O += P V : 3-term (P hi/lo split, proven at rel_err 1.7e-5)
        #pragma unroll
        for (int kc = 0; kc < 4; kc++) {
            uint32_t pah[4], pal[4];
            split2(sa[2 * kc][0],     sa[2 * kc][1],     pah[0], pal[0]);
            split2(sa[2 * kc][2],     sa[2 * kc][3],     pah[1], pal[1]);
            split2(sa[2 * kc + 1][0], sa[2 * kc + 1][1], pah[2], pal[2]);
            split2(sa[2 * kc + 1][2], sa[2 * kc + 1][3], pah[3], pal[3]);

            uint32_t vbh[8][2], vbl[8][2];
            #pragma unroll
            for (int nt = 0; nt < 8; nt++) {
                uint32_t ad = (nt * 8 + frow) * FSTRIDE_B + (kc * 16 + 2 * fcol) * 2;
                vbh[nt][0] = lds32(Vh + ad);
                vbh[nt][1] = lds32(Vh + ad + 16);
                vbl[nt][0] = lds32(Vl + ad);
                vbl[nt][1] = lds32(Vl + ad + 16);
            }
            #pragma unroll
            for (int nt = 0; nt < 8; nt++) mma_bf16(o[nt], pah, vbh[nt]);
            #pragma unroll
            for (int nt = 0; nt < 8; nt++) mma_bf16(o[nt], pah, vbl[nt]);
            #pragma unroll
            for (int nt = 0; nt < 8; nt++) mma_bf16(o[nt], pal, vbh[nt]);
        }

        __syncthreads();
        if (kt + 2 < NKT) load_stage(s, kt + 2);
        else asm volatile("cp.async.commit_group;\n" ::: "memory");
    }

    float i0 = 1.f / l0, i1 = 1.f / l1;
    size_t ob = ((size_t)(bh >> 4) * T_SEQ + qt * 64 + wid * 16) * CDIM + (bh & 15) * HDIM;
    #pragma unroll
    for (int nt = 0; nt < 8; nt++) {
        int cg = nt * 8 + 2 * fcol;
        uint32_t h0, lo0, h1, lo1;
        split2(o[nt][0] * i0, o[nt][1] * i0, h0, lo0);
        split2(o[nt][2] * i1, o[nt][3] * i1, h1, lo1);
        size_t p0 = (ob + (size_t)frow * CDIM + cg) >> 1;
        size_t p1 = (ob + (size_t)(frow + 8) * CDIM + cg) >> 1;
        ((uint32_t*)oh)[p0] = h0;
        ((uint32_t*)ol)[p0] = lo0;
        ((uint32_t*)oh)[p1] = h1;
        ((uint32_t*)ol)[p1] = lo1;
    }
}

// ---------------------------------------------------------------------------
// Launch
// ---------------------------------------------------------------------------
extern "C" void kernel_launch(void* const* d_in, const int* in_sizes, int n_in,
                              void* d_out, int out_size)
{
    const float* x    = (const float*)d_in[0];
    const float* Wqkv = (const float*)d_in[1];
    const float* Wout = (const float*)d_in[2];
    const float* bout = (const float*)d_in[3];
    float* out = (float*)d_out;

    void *pqkv, *pxbh, *pxbl, *pwbh, *pwbl, *pobh, *pobl, *pabh, *pabl;
    void *pqbh, *pqbl, *pkbh, *pkbl, *pvth, *pvtl;
    cudaGetSymbolAddress(&pqkv, g_qkv);
    cudaGetSymbolAddress(&pxbh, g_xbh);
    cudaGetSymbolAddress(&pxbl, g_xbl);
    cudaGetSymbolAddress(&pwbh, g_wbh);
    cudaGetSymbolAddress(&pwbl, g_wbl);
    cudaGetSymbolAddress(&pobh, g_obh);
    cudaGetSymbolAddress(&pobl, g_obl);
    cudaGetSymbolAddress(&pabh, g_abh);
    cudaGetSymbolAddress(&pabl, g_abl);
    cudaGetSymbolAddress(&pqbh, g_qbh);
    cudaGetSymbolAddress(&pqbl, g_qbl);
    cudaGetSymbolAddress(&pkbh, g_kbh);
    cudaGetSymbolAddress(&pkbl, g_kbl);
    cudaGetSymbolAddress(&pvth, g_vth);
    cudaGetSymbolAddress(&pvtl, g_vtl);
    float* qkv = (float*)pqkv;

    cudaFuncSetAttribute(gemm_bf16x3,
                         cudaFuncAttributeMaxDynamicSharedMemorySize, GEMM_SMEM);
    cudaFuncSetAttribute(flash_mma,
                         cudaFuncAttributeMaxDynamicSharedMemorySize, FLASH_SMEM);

    split_bf16<<<(MROWS * CDIM / 4) / 256, 256>>>(x, (__nv_bfloat16*)pxbh, (__nv_bfloat16*)pxbl);
    split_bf16<<<(3 * CDIM * CDIM / 4) / 256, 256>>>(Wqkv, (__nv_bfloat16*)pwbh, (__nv_bfloat16*)pwbl);
    split_bf16<<<(CDIM * CDIM / 4) / 256, 256>>>(Wout, (__nv_bfloat16*)pobh, (__nv_bfloat16*)pobl);

    gemm_bf16x3<<<dim3(3 * CDIM / 64, MROWS / 128), 128, GEMM_SMEM>>>(
        (const __nv_bfloat16*)pxbh, (const __nv_bfloat16*)pxbl,
        (const __nv_bfloat16*)pwbh, (const __nv_bfloat16*)pwbl,
        qkv, nullptr, MROWS, 3 * CDIM, CDIM);

    rope_bsplit<<<(BH * T_SEQ * 32) / 256, 256>>>(
        qkv, (__nv_bfloat16*)pqbh, (__nv_bfloat16*)pqbl,
        (__nv_bfloat16*)pkbh, (__nv_bfloat16*)pkbl);
    vsplit_t<<<dim3(T_SEQ / 64, BH), 256>>>(
        qkv, (__nv_bfloat16*)pvth, (__nv_bfloat16*)pvtl);

    flash_mma<<<dim3(T_SEQ / 64, BH), 128, FLASH_SMEM>>>(
        (const __nv_bfloat16*)pqbh, (const __nv_bfloat16*)pqbl,
        (const __nv_bfloat16*)pkbh, (const __nv_bfloat16*)pkbl,
        (const __nv_bfloat16*)pvth, (const __nv_bfloat16*)pvtl,
        (__nv_bfloat16*)pabh, (__nv_bfloat16*)pabl);

    gemm_bf16x3<<<dim3(CDIM / 64, MROWS / 128), 128, GEMM_SMEM>>>(
        (const __nv_bfloat16*)pabh, (const __nv_bfloat16*)pabl,
        (const __nv_bfloat16*)pobh, (const __nv_bfloat16*)pobl,
        out, bout, MROWS, CDIM, CDIM);
}